// round 5
// baseline (speedup 1.0000x reference)
#include <cuda_runtime.h>

#define CM_B    64
#define CM_T    256
#define CM_NI   512
#define CM_NO   512
#define CM_NOBS 128
#define ROWS_PER_WARP   4
#define WARPS_PER_BLOCK 2
#define THREADS (WARPS_PER_BLOCK * 32)
#define X_ROW_U2 (CM_NI / 4)   // 128 ulonglong2 per 512-float row
#define FULLM 0xffffffffu

typedef unsigned long long u64;

__device__ __forceinline__ u64 pk2(float lo, float hi) {
    u64 r; asm("mov.b64 %0, {%1, %2};" : "=l"(r) : "f"(lo), "f"(hi)); return r;
}
__device__ __forceinline__ float2 upk2(u64 v) {
    float2 f; asm("mov.b64 {%0, %1}, %2;" : "=f"(f.x), "=f"(f.y) : "l"(v)); return f;
}
__device__ __forceinline__ u64 ffma2(u64 a, u64 b, u64 c) {
    u64 d; asm("fma.rn.f32x2 %0, %1, %2, %3;" : "=l"(d) : "l"(a), "l"(b), "l"(c)); return d;
}
__device__ __forceinline__ u64 fadd2(u64 a, u64 b) {
    u64 d; asm("add.rn.f32x2 %0, %1, %2;" : "=l"(d) : "l"(a), "l"(b)); return d;
}
__device__ __forceinline__ float sigmoidf_fast(float v) {
    return __fdividef(1.0f, 1.0f + __expf(-v));
}

// One warp = 4 contiguous observed slots of one batch.
// Lane l owns float4-chunks {k*32 + l, k=0..3} of each 512-float vector.
// Lookahead identity: pre_{t+1} = (w_t . x_{t+1}) + 0.01*y_t*(x_t . x_{t+1})
// keeps the dot + butterfly OFF the serial chain (they only need w_t).
__global__ __launch_bounds__(THREADS, 8)
void circuit_kernel(const float* __restrict__ X,
                    const float* __restrict__ Wi,
                    const int*   __restrict__ obs,
                    float*       __restrict__ out) {
    const int b    = blockIdx.x;
    const int warp = threadIdx.x >> 5;
    const int lane = threadIdx.x & 31;
    const int wg   = blockIdx.y * WARPS_PER_BLOCK + warp;  // 0..31
    const int j0   = wg * ROWS_PER_WARP;

    const int  g       = lane >> 3;            // row group 0..3
    const bool sel1    = (g == 1);
    const bool sel2    = (g == 2);
    const bool sel3    = (g == 3);
    const bool st_pred = (lane & 7) == 0;      // lanes 0,8,16,24 store rows 0..3

    // ---- load W rows (coalesced lane layout) ----
    u64 w[ROWS_PER_WARP][8];
    #pragma unroll
    for (int r = 0; r < ROWS_PER_WARP; ++r) {
        const int o = __ldg(&obs[j0 + r]);
        const ulonglong2* wp =
            (const ulonglong2*)(Wi + ((size_t)b * CM_NO + o) * CM_NI) + lane;
        #pragma unroll
        for (int k = 0; k < 4; ++k) {
            ulonglong2 v = __ldg(wp + k * 32);
            w[r][2 * k]     = v.x;
            w[r][2 * k + 1] = v.y;
        }
    }

    const ulonglong2* xb = (const ulonglong2*)(X + (size_t)b * CM_T * CM_NI) + lane;
    float* opl = out + (size_t)b * CM_T * CM_NOBS + j0 + g;   // used iff st_pred

    // preload x_0 -> A, x_1 -> B
    u64 xA[8], xB[8];
    #pragma unroll
    for (int k = 0; k < 4; ++k) {
        ulonglong2 v = __ldg(xb + k * 32);
        xA[2 * k] = v.x; xA[2 * k + 1] = v.y;
        ulonglong2 u = __ldg(xb + X_ROW_U2 + k * 32);
        xB[2 * k] = u.x; xB[2 * k + 1] = u.y;
    }
    const ulonglong2* pf = xb + 2 * X_ROW_U2;   // next prefetch: x_2

    // 4 dots of w against v, 2 packed chains each -> per-lane partials
    auto dot4 = [&](const u64* __restrict__ v, float* __restrict__ D) {
        #pragma unroll
        for (int r = 0; r < ROWS_PER_WARP; ++r) {
            u64 a0 = ffma2(w[r][0], v[0], pk2(0.f, 0.f));
            u64 a1 = ffma2(w[r][1], v[1], pk2(0.f, 0.f));
            #pragma unroll
            for (int k = 2; k < 8; k += 2) {
                a0 = ffma2(w[r][k],     v[k],     a0);
                a1 = ffma2(w[r][k + 1], v[k + 1], a1);
            }
            float2 s = upk2(fadd2(a0, a1));
            D[r] = s.x + s.y;
        }
    };

    // butterfly reduce {D0..D3, gg}; returns this group's row-dot; gg fully reduced
    auto reduce5 = [&](float* __restrict__ D, float& gg) -> float {
        #pragma unroll
        for (int d = 16; d >= 8; d >>= 1) {
            #pragma unroll
            for (int r = 0; r < ROWS_PER_WARP; ++r)
                D[r] += __shfl_xor_sync(FULLM, D[r], d);
            gg += __shfl_xor_sync(FULLM, gg, d);
        }
        float v = D[0];
        if (sel1) v = D[1];
        if (sel2) v = D[2];
        if (sel3) v = D[3];
        #pragma unroll
        for (int d = 4; d >= 1; d >>= 1) {
            v  += __shfl_xor_sync(FULLM, v,  d);
            gg += __shfl_xor_sync(FULLM, gg, d);
        }
        return v;
    };

    // ---- t = 0: direct dot w.x_0 ----
    float yv;   // this group's latest y
    {
        float D[ROWS_PER_WARP];
        dot4(xA, D);
        float gg = 0.f;
        float v = reduce5(D, gg);
        yv = sigmoidf_fast(v);
        if (st_pred) *opl = yv;
        opl += CM_NOBS;
    }

    // step: cur = x_t, nxt = x_{t+1}; produces y_{t+1}; prefetches x_{t+2} into cur
    auto step = [&](u64* __restrict__ cur, const u64* __restrict__ nxt, bool pre) {
        // D = w_t . x_{t+1}  (reads w BEFORE update below)
        float D[ROWS_PER_WARP];
        dot4(nxt, D);

        // gg = x_t . x_{t+1}
        u64 a0 = ffma2(cur[0], nxt[0], pk2(0.f, 0.f));
        u64 a1 = ffma2(cur[1], nxt[1], pk2(0.f, 0.f));
        #pragma unroll
        for (int k = 2; k < 8; k += 2) {
            a0 = ffma2(cur[k],     nxt[k],     a0);
            a1 = ffma2(cur[k + 1], nxt[k + 1], a1);
        }
        float2 s = upk2(fadd2(a0, a1));
        float gg = s.x + s.y;

        // w_{t+1} = w_t + 0.01*y_t*x_t   (y_t broadcast per row; off serial chain)
        const float y0 = __shfl_sync(FULLM, yv, 0);
        const float y1 = __shfl_sync(FULLM, yv, 8);
        const float y2 = __shfl_sync(FULLM, yv, 16);
        const float y3 = __shfl_sync(FULLM, yv, 24);
        u64 cc[ROWS_PER_WARP] = {
            pk2(0.01f * y0, 0.01f * y0), pk2(0.01f * y1, 0.01f * y1),
            pk2(0.01f * y2, 0.01f * y2), pk2(0.01f * y3, 0.01f * y3) };
        #pragma unroll
        for (int r = 0; r < ROWS_PER_WARP; ++r)
            #pragma unroll
            for (int k = 0; k < 8; ++k)
                w[r][k] = ffma2(cc[r], cur[k], w[r][k]);

        // prefetch x_{t+2} into the slot x_t just vacated
        if (pre) {
            #pragma unroll
            for (int k = 0; k < 4; ++k) {
                ulonglong2 v2 = __ldg(pf + k * 32);
                cur[2 * k] = v2.x; cur[2 * k + 1] = v2.y;
            }
        }
        pf += X_ROW_U2;

        // reduce; serial tail: 1 FFMA + sigmoid
        float v = reduce5(D, gg);
        const float cgy = 0.01f * gg;
        v = __fmaf_rn(cgy, yv, v);
        yv = sigmoidf_fast(v);
        if (st_pred) *opl = yv;
        opl += CM_NOBS;
    };

    // steps k = 0..254 produce y_1..y_255 (127 double iters + 1 tail)
    #pragma unroll 1
    for (int t = 0; t < CM_T - 2; t += 2) {
        step(xA, xB, true);    // cur=x_t,   nxt=x_{t+1}, prefetch x_{t+2}->A
        step(xB, xA, true);    // cur=x_{t+1}, nxt=x_{t+2}, prefetch x_{t+3}->B
    }
    step(xA, xB, false);       // cur=x_254, nxt=x_255 -> y_255, no prefetch
}

extern "C" void kernel_launch(void* const* d_in, const int* in_sizes, int n_in,
                              void* d_out, int out_size) {
    const float* X   = (const float*)d_in[0];
    const float* Wi  = (const float*)d_in[1];
    const int*   obs = (const int*)d_in[2];
    float*       out = (float*)d_out;

    dim3 grid(CM_B, CM_NOBS / (ROWS_PER_WARP * WARPS_PER_BLOCK));  // 64 x 16
    circuit_kernel<<<grid, THREADS>>>(X, Wi, obs, out);
}